// round 7
// baseline (speedup 1.0000x reference)
#include <cuda_runtime.h>
#include <cstdint>

#define BATCH 4
#define SEQ   2048
#define INF   4096
#define OUTF  4096
#define RANK  16
// SCALING = 16/16 = 1.0f (elided)

// ---- phase-1 ----
#define SPLITS 8
#define KSPLIT (INF / SPLITS)      // 512
#define CHUNK  32
#define NCH    (KSPLIT / CHUNK)    // 16
#define T1     512                 // 2 rank-groups x 256 lanes
#define LANES  256
#define LROWS  2                   // rows per thread
#define ROWS1  512
#define XP     36                  // floats; conflict-free LDS.128 (8-lane phases)
#define XSTG   (ROWS1 * XP)        // 18432 floats
#define BSTG   (RANK * CHUNK)      // 512 floats
#define STG_F  (XSTG + BSTG)       // 18944 floats
#define SMEM1  (2 * STG_F * 4)     // 151552 B

// ---- phase-2 ----
#define T2     256
#define ROWS2  128
#define OPT    4
#define OTILE  (T2 * OPT)          // 1024
#define BXP    9

typedef unsigned long long ull;

__device__ float g_bx[SPLITS * BATCH * SEQ * RANK];   // 4 MB split partials

// ---- helpers --------------------------------------------------------------
__device__ __forceinline__ void fma2(ull& d, ull a, ull b) {
    asm("fma.rn.f32x2 %0, %1, %2, %0;" : "+l"(d) : "l"(a), "l"(b));
}
__device__ __forceinline__ ull pack2(float lo, float hi) {
    ull d; asm("mov.b64 %0, {%1, %2};" : "=l"(d) : "f"(lo), "f"(hi)); return d;
}
__device__ __forceinline__ void unpack2(float& lo, float& hi, ull d) {
    asm("mov.b64 {%0, %1}, %2;" : "=f"(lo), "=f"(hi) : "l"(d));
}
__device__ __forceinline__ void cp16(uint32_t dst, const float* src) {
    asm volatile("cp.async.cg.shared.global [%0], [%1], 16;" :: "r"(dst), "l"(src));
}
__device__ __forceinline__ void cp_commit() {
    asm volatile("cp.async.commit_group;");
}
__device__ __forceinline__ void cp_wait0() {
    asm volatile("cp.async.wait_group 0;");
}

// ---------------------------------------------------------------------------
// Phase 1: Bx_part[s][b][n][r] = sum_{k in split s} x[b][n][k] * B[aid][r][k]
// T1=512 = 2 rank-groups (8 ranks) x 256 lanes; 2 rows/thread.
// Per warp-j: 2 x-LDS.128 (conflict-free) + 8 B-LDS.128 (broadcast) + 32 fma2.
// 2-stage cp.async.cg(16B) pipeline, one barrier per chunk. 16 warps/SM.
// ---------------------------------------------------------------------------
__global__ __launch_bounds__(T1, 1) void lora_phase1(
    const float* __restrict__ x,
    const float* __restrict__ Bw,
    const int*   __restrict__ ids)
{
    extern __shared__ float sm[];

    const int tid = threadIdx.x;
    const int n0  = blockIdx.x * ROWS1;
    const int b   = blockIdx.y;
    const int s   = blockIdx.z;
    const int aid = ids[b];
    const int k0  = s * KSPLIT;
    const int g   = tid >> 8;            // rank group: ranks g*8 .. g*8+7
    const int lt  = tid & 255;           // rows lt, lt+256

    const float* xbase = x  + (size_t)b * SEQ * INF;
    const float* Bbase = Bw + (size_t)aid * RANK * INF;
    const uint32_t smb = (uint32_t)__cvta_generic_to_shared(sm);

    auto issue = [&](int ch, int st) {
        const int cc = k0 + ch * CHUNK;
        const uint32_t sb = smb + (uint32_t)(st * STG_F) * 4u;
        // x tile: 512 rows x 8 float4 -> 8 cp16/thread (8 lanes per 128B segment)
#pragma unroll
        for (int i = 0; i < 8; ++i) {
            const int f   = i * T1 + tid;
            const int row = f >> 3, j4 = f & 7;
            cp16(sb + (uint32_t)(row * XP + 4 * j4) * 4u,
                 xbase + (size_t)(n0 + row) * INF + cc + 4 * j4);
        }
        // B tile: 16 ranks x 8 float4 -> threads 0..127
        if (tid < 128) {
            const int r = tid >> 3, j4 = tid & 7;
            cp16(sb + (uint32_t)(XSTG + r * CHUNK + 4 * j4) * 4u,
                 Bbase + (size_t)r * INF + cc + 4 * j4);
        }
    };

    ull acc[8][LROWS];
#pragma unroll
    for (int r = 0; r < 8; ++r)
#pragma unroll
        for (int q = 0; q < LROWS; ++q) acc[r][q] = 0ull;

    issue(0, 0); cp_commit();

#pragma unroll 1
    for (int ch = 0; ch < NCH; ++ch) {
        cp_wait0();
        __syncthreads();                 // chunk ch visible; the stage about to
                                         // be overwritten was consumed in ch-1
        if (ch + 1 < NCH) { issue(ch + 1, (ch + 1) & 1); cp_commit(); }

        const float* xs  = sm + (ch & 1) * STG_F;
        const float* bsm = xs + XSTG + g * 8 * CHUNK;
#pragma unroll
        for (int j = 0; j < CHUNK / 4; ++j) {    // 8 iters of 4 k's
            const float4 xv0 = *(const float4*)(xs + lt * XP + 4 * j);
            const float4 xv1 = *(const float4*)(xs + (lt + 256) * XP + 4 * j);
            const ull xa0 = pack2(xv0.x, xv0.y), xa1 = pack2(xv0.z, xv0.w);
            const ull xb0 = pack2(xv1.x, xv1.y), xb1 = pack2(xv1.z, xv1.w);
#pragma unroll
            for (int r = 0; r < 8; ++r) {
                const ulonglong2 bv =
                    *(const ulonglong2*)(bsm + r * CHUNK + 4 * j);  // broadcast
                fma2(acc[r][0], xa0, bv.x);
                fma2(acc[r][0], xa1, bv.y);
                fma2(acc[r][1], xb0, bv.x);
                fma2(acc[r][1], xb1, bv.y);
            }
        }
    }

    // horizontal pair-add; store 8 ranks x 2 rows
    const size_t slot = ((size_t)s * BATCH + b) * SEQ;
#pragma unroll
    for (int q = 0; q < LROWS; ++q) {
        float* d = g_bx + (slot + n0 + lt + 256 * q) * RANK + g * 8;
        float l, h; float4 v0, v1;
        unpack2(l, h, acc[0][q]); v0.x = l + h;
        unpack2(l, h, acc[1][q]); v0.y = l + h;
        unpack2(l, h, acc[2][q]); v0.z = l + h;
        unpack2(l, h, acc[3][q]); v0.w = l + h;
        unpack2(l, h, acc[4][q]); v1.x = l + h;
        unpack2(l, h, acc[5][q]); v1.y = l + h;
        unpack2(l, h, acc[6][q]); v1.z = l + h;
        unpack2(l, h, acc[7][q]); v1.w = l + h;
        ((float4*)d)[0] = v0;
        ((float4*)d)[1] = v1;
    }
}

// ---------------------------------------------------------------------------
// Phase 2 (fused split-reduce): out[b][n][o] = sum_r Bx[b][n][r]*A[aid][o][r]
// Thread owns 4 consecutive o; A pairs (32 ull) in regs; Bx dup'd in smem.
// 2 rows/iter -> 8 independent fma2 chains. 2 CTAs/SM (16 warps).
// ---------------------------------------------------------------------------
__global__ __launch_bounds__(T2, 2) void lora_phase2(
    const float* __restrict__ Aw,
    const int*   __restrict__ ids,
    float*       __restrict__ out)
{
    __shared__ ulonglong2 bxd[ROWS2 * BXP];      // 18.4 KB

    const int tid = threadIdx.x;
    const int o   = blockIdx.x * OTILE + tid * OPT;
    const int n0  = blockIdx.y * ROWS2;
    const int b   = blockIdx.z;
    const int aid = ids[b];

    // A pairs: ap01[r] = (A[o][r], A[o+1][r]); ap23[r] = (A[o+2][r], A[o+3][r])
    ull ap01[16], ap23[16];
    {
        const float* Ab = Aw + ((size_t)aid * OUTF + o) * RANK;
        float a0[16], a1[16], a2[16], a3[16];
#pragma unroll
        for (int j = 0; j < 4; ++j) {
            float4 v;
            v = *(const float4*)(Ab + 0 * RANK + 4 * j);
            a0[4*j]=v.x; a0[4*j+1]=v.y; a0[4*j+2]=v.z; a0[4*j+3]=v.w;
            v = *(const float4*)(Ab + 1 * RANK + 4 * j);
            a1[4*j]=v.x; a1[4*j+1]=v.y; a1[4*j+2]=v.z; a1[4*j+3]=v.w;
            v = *(const float4*)(Ab + 2 * RANK + 4 * j);
            a2[4*j]=v.x; a2[4*j+1]=v.y; a2[4*j+2]=v.z; a2[4*j+3]=v.w;
            v = *(const float4*)(Ab + 3 * RANK + 4 * j);
            a3[4*j]=v.x; a3[4*j+1]=v.y; a3[4*j+2]=v.z; a3[4*j+3]=v.w;
        }
#pragma unroll
        for (int r = 0; r < 16; ++r) {
            ap01[r] = pack2(a0[r], a1[r]);
            ap23[r] = pack2(a2[r], a3[r]);
        }
    }

    // fused reduce + duplicate staging: 2 threads per row, 8 ranks each
    {
        const int row  = tid >> 1;
        const int half = tid & 1;
        const float* base = g_bx + ((size_t)b * SEQ + n0 + row) * RANK + half * 8;
        float4 u = make_float4(0.f, 0.f, 0.f, 0.f);
        float4 v = make_float4(0.f, 0.f, 0.f, 0.f);
#pragma unroll
        for (int s = 0; s < SPLITS; ++s) {
            const float4* p =
                (const float4*)(base + (size_t)s * BATCH * SEQ * RANK);
            const float4 pa = p[0], pb = p[1];
            u.x += pa.x; u.y += pa.y; u.z += pa.z; u.w += pa.w;
            v.x += pb.x; v.y += pb.y; v.z += pb.z; v.w += pb.w;
        }
        const float w[8] = {u.x, u.y, u.z, u.w, v.x, v.y, v.z, v.w};
#pragma unroll
        for (int i = 0; i < 4; ++i) {
            ulonglong2 e;
            e.x = pack2(w[2*i],   w[2*i]);
            e.y = pack2(w[2*i+1], w[2*i+1]);
            bxd[row * BXP + half * 4 + i] = e;
        }
    }
    __syncthreads();

    float4* outp = (float4*)(out + ((size_t)b * SEQ + n0) * OUTF + o);

#pragma unroll 1
    for (int n = 0; n < ROWS2; n += 2) {
        const ulonglong2* r0 = bxd + n * BXP;
        const ulonglong2* r1 = r0 + BXP;
        ull A0=0, A1=0, A2=0, A3=0, B0=0, B1=0, B2=0, B3=0;
#pragma unroll
        for (int p = 0; p < 4; ++p) {            // ranks 0-7
            const ulonglong2 ba = r0[p], bb = r1[p];
            fma2(A0, ap01[2*p], ba.x); fma2(A0, ap01[2*p+1], ba.y);
            fma2(A1, ap23[2*p], ba.x); fma2(A1, ap23[2*p+1], ba.y);
            fma2(B0, ap01[2*p], bb.x); fma2(B0, ap01[2*p+1], bb.y);
            fma2(B1, ap23[2*p], bb.x); fma2(B1, ap23[2*p+1], bb.y);
        }
#pragma unroll
        for (int p = 4; p < 8; ++p) {            // ranks 8-15
            const ulonglong2 ba = r0[p], bb = r1[p];
            fma2(A2, ap01[2*p], ba.x); fma2(A2, ap01[2*p+1], ba.y);
            fma2(A3, ap23[2*p], ba.x); fma2(A3, ap23[2*p+1], ba.y);
            fma2(B2, ap01[2*p], bb.x); fma2(B2, ap01[2*p+1], bb.y);
            fma2(B3, ap23[2*p], bb.x); fma2(B3, ap23[2*p+1], bb.y);
        }
        float4 res0, res1;
        float l0, h0, l1, h1;
        unpack2(l0, h0, A0); unpack2(l1, h1, A2); res0.x = l0+l1; res0.y = h0+h1;
        unpack2(l0, h0, A1); unpack2(l1, h1, A3); res0.z = l0+l1; res0.w = h0+h1;
        unpack2(l0, h0, B0); unpack2(l1, h1, B2); res1.x = l0+l1; res1.y = h0+h1;
        unpack2(l0, h0, B1); unpack2(l1, h1, B3); res1.z = l0+l1; res1.w = h0+h1;
        outp[(size_t)n       * (OUTF / 4)] = res0;
        outp[(size_t)(n + 1) * (OUTF / 4)] = res1;
    }
}

// ---------------------------------------------------------------------------
extern "C" void kernel_launch(void* const* d_in, const int* in_sizes, int n_in,
                              void* d_out, int out_size)
{
    const float* x   = (const float*)d_in[0];   // [4,2048,4096]
    const float* Aw  = (const float*)d_in[1];   // [8,4096,16]
    const float* Bw  = (const float*)d_in[2];   // [8,16,4096]
    const int*   ids = (const int*)  d_in[3];   // [4]
    float*       out = (float*)d_out;           // [4,2048,4096]

    cudaFuncSetAttribute(lora_phase1,
                         cudaFuncAttributeMaxDynamicSharedMemorySize, SMEM1);

    dim3 g1(SEQ / ROWS1, BATCH, SPLITS);        // (4,4,8) = 128 CTAs
    lora_phase1<<<g1, T1, SMEM1>>>(x, Bw, ids);

    dim3 g2(OUTF / OTILE, SEQ / ROWS2, BATCH);  // (4,16,4) = 256 CTAs
    lora_phase2<<<g2, T2>>>(Aw, ids, out);
}